// round 5
// baseline (speedup 1.0000x reference)
#include <cuda_runtime.h>
#include <cstdint>

#define B_ 64
#define T_ 512
#define I_ 512
#define H_ 1024

// ---------------- scratch: small statics only (proven safe in R3) ----------------
__device__ float g_h[2][B_ * H_];        // h double buffer (512 KB)

// ---------------- packed fp32x2 FMA helpers (FFMA2: only reachable via PTX) ------
__device__ __forceinline__ unsigned long long ffma2(
    unsigned long long a, unsigned long long b, unsigned long long c)
{
    unsigned long long d;
    asm("fma.rn.f32x2 %0, %1, %2, %3;" : "=l"(d) : "l"(a), "l"(b), "l"(c));
    return d;
}
__device__ __forceinline__ float2 unpack2(unsigned long long v) {
    float2 r;
    asm("mov.b64 {%0, %1}, %2;" : "=f"(r.x), "=f"(r.y) : "l"(v));
    return r;
}

// ---------------- init: zero h0 each launch (step 511 dirties buffer 0) ----------------
__global__ void init_h0_kernel() {
    int i = blockIdx.x * blockDim.x + threadIdx.x;
    if (i < B_ * H_) g_h[0][i] = 0.0f;
}

// ---------------- pre-GEMM: out[b][t][n] = sum_k x[b][t][k]*Wi[n][k] + bi[n] + bh[n] ----
// unchanged from passing R3 kernel
__global__ __launch_bounds__(256) void gemm_pre_kernel(
    const float* __restrict__ x, const float* __restrict__ Wi,
    const float* __restrict__ bi, const float* __restrict__ bh,
    float* __restrict__ out)
{
    __shared__ float As[16][68];
    __shared__ float Bs[16][68];

    const int tid = threadIdx.x;
    const int tx = tid & 15;
    const int ty = tid >> 4;
    const int mbase = blockIdx.y * 64;
    const int nbase = blockIdx.x * 64;

    const int lrow = tid >> 2;
    const int lkq  = (tid & 3) * 4;

    const int m_l = mbase + lrow;
    const float* arow = x + (size_t)(m_l & 63) * (T_ * I_) + (size_t)(m_l >> 6) * I_;
    const float* brow = Wi + (size_t)(nbase + lrow) * I_;

    float acc[4][4];
#pragma unroll
    for (int i = 0; i < 4; i++)
#pragma unroll
        for (int j = 0; j < 4; j++) acc[i][j] = 0.0f;

    for (int k0 = 0; k0 < I_; k0 += 16) {
        float4 a4 = *(const float4*)(arow + k0 + lkq);
        float4 b4 = *(const float4*)(brow + k0 + lkq);
        __syncthreads();
        As[lkq + 0][lrow] = a4.x; As[lkq + 1][lrow] = a4.y;
        As[lkq + 2][lrow] = a4.z; As[lkq + 3][lrow] = a4.w;
        Bs[lkq + 0][lrow] = b4.x; Bs[lkq + 1][lrow] = b4.y;
        Bs[lkq + 2][lrow] = b4.z; Bs[lkq + 3][lrow] = b4.w;
        __syncthreads();
#pragma unroll
        for (int kk = 0; kk < 16; kk++) {
            float a0 = As[kk][ty * 4 + 0], a1 = As[kk][ty * 4 + 1];
            float a2 = As[kk][ty * 4 + 2], a3 = As[kk][ty * 4 + 3];
            float b0 = Bs[kk][tx * 4 + 0], b1 = Bs[kk][tx * 4 + 1];
            float b2 = Bs[kk][tx * 4 + 2], b3 = Bs[kk][tx * 4 + 3];
            acc[0][0] += a0 * b0; acc[0][1] += a0 * b1; acc[0][2] += a0 * b2; acc[0][3] += a0 * b3;
            acc[1][0] += a1 * b0; acc[1][1] += a1 * b1; acc[1][2] += a1 * b2; acc[1][3] += a1 * b3;
            acc[2][0] += a2 * b0; acc[2][1] += a2 * b1; acc[2][2] += a2 * b2; acc[2][3] += a2 * b3;
            acc[3][0] += a3 * b0; acc[3][1] += a3 * b1; acc[3][2] += a3 * b2; acc[3][3] += a3 * b3;
        }
    }

    const int n0 = nbase + tx * 4;
    float bias0 = bi[n0 + 0] + bh[n0 + 0];
    float bias1 = bi[n0 + 1] + bh[n0 + 1];
    float bias2 = bi[n0 + 2] + bh[n0 + 2];
    float bias3 = bi[n0 + 3] + bh[n0 + 3];
#pragma unroll
    for (int i = 0; i < 4; i++) {
        int m = mbase + ty * 4 + i;
        int b = m & 63;
        int t = m >> 6;
        float4 o;
        o.x = acc[i][0] + bias0; o.y = acc[i][1] + bias1;
        o.z = acc[i][2] + bias2; o.w = acc[i][3] + bias3;
        *(float4*)(out + (size_t)b * (T_ * H_) + (size_t)t * H_ + n0) = o;
    }
}

// ---------------- per-step scan: out[b][t][:] = relu(out[b][t][:] + hprev @ Wh^T) ------
// 128 blocks x 512 threads. Block owns j-tile of 8 (Wh rows in smem, staged per step).
// Thread = exactly one (b, j): b = tid>>3, j = tid&7. FFMA2-packed k loop, ILP 4.
__global__ __launch_bounds__(512) void scan_step_kernel(
    const float* __restrict__ Wh,
    float* __restrict__ out,
    int t, int is_last)
{
    __shared__ float whs[8][1028];   // +4 pad: rows 4 banks apart -> conflict-free
    const int tid = threadIdx.x;
    const int jbase = blockIdx.x * 8;

    // stage Wh rows jbase..jbase+7 (32 KB) from L2
    for (int idx = tid; idx < 2048; idx += 512) {
        int j = idx >> 8;
        int kq = (idx & 255) * 4;
        *(float4*)&whs[j][kq] = *(const float4*)(Wh + (size_t)(jbase + j) * H_ + kq);
    }
    __syncthreads();

    const int b = tid >> 3;      // 0..63
    const int j = tid & 7;       // 0..7

    const float* hrow = g_h[t & 1] + b * H_;
    float* hnext      = g_h[(t + 1) & 1];
    const float* wrow = &whs[j][0];

    // 4 packed accumulators (8 fp32 lanes), k packed in pairs
    unsigned long long acc0 = 0ull, acc1 = 0ull, acc2 = 0ull, acc3 = 0ull;
#pragma unroll 4
    for (int k = 0; k < H_; k += 8) {
        ulonglong2 hA = *(const ulonglong2*)(hrow + k);
        ulonglong2 hB = *(const ulonglong2*)(hrow + k + 4);
        ulonglong2 wA = *(const ulonglong2*)(wrow + k);
        ulonglong2 wB = *(const ulonglong2*)(wrow + k + 4);
        acc0 = ffma2(hA.x, wA.x, acc0);
        acc1 = ffma2(hA.y, wA.y, acc1);
        acc2 = ffma2(hB.x, wB.x, acc2);
        acc3 = ffma2(hB.y, wB.y, acc3);
    }
    float2 p0 = unpack2(acc0);
    float2 p1 = unpack2(acc1);
    float2 p2 = unpack2(acc2);
    float2 p3 = unpack2(acc3);
    float acc = ((p0.x + p0.y) + (p1.x + p1.y)) + ((p2.x + p2.y) + (p3.x + p3.y));

    // in-place: pre lives in out[b][t][:]; write activated value back
    float* oel = out + (size_t)b * (T_ * H_) + (size_t)t * H_ + jbase + j;
    float v = fmaxf(acc + *oel, 0.0f);
    *oel = v;

    const size_t hb = (size_t)b * H_ + jbase + j;
    hnext[hb] = v;
    if (is_last) {
        float* hid = out + (size_t)B_ * T_ * H_;
        hid[hb] = v;
    }
}

// ---------------- launch: kernel launches only ----------------
extern "C" void kernel_launch(void* const* d_in, const int* in_sizes, int n_in,
                              void* d_out, int out_size)
{
    const float* x  = (const float*)d_in[0];
    const float* Wi = (const float*)d_in[1];
    const float* bi = (const float*)d_in[2];
    const float* Wh = (const float*)d_in[3];
    const float* bh = (const float*)d_in[4];
    float* out = (float*)d_out;

    init_h0_kernel<<<64, 1024>>>();
    dim3 grid_gemm(H_ / 64, (T_ * B_) / 64);   // (16, 512)
    gemm_pre_kernel<<<grid_gemm, 256>>>(x, Wi, bi, bh, out);

    for (int t = 0; t < T_; t++) {
        scan_step_kernel<<<128, 512>>>(Wh, out, t, t == T_ - 1);
    }
}

// round 6
// speedup vs baseline: 2.2035x; 2.2035x over previous
#include <cuda_runtime.h>
#include <cstdint>

#define B_ 64
#define T_ 512
#define I_ 512
#define H_ 1024

// scan tiling
#define BT_ 16                 // b per block
#define JT_ 32                 // j per block
#define SCAN_THREADS 256
#define HS_PITCH 1028          // floats per h_s row (pad 4)
#define WS_PITCH 1028          // floats per w_s row (pad 4)
#define HS_FLOATS (BT_ * HS_PITCH)            // 16448
#define WS_FLOATS (JT_ * WS_PITCH)            // 32896
#define SCAN_SMEM_BYTES ((HS_FLOATS + WS_FLOATS) * 4)   // 197376

// ---------------- scratch: small statics only ----------------
__device__ float g_h[2][B_ * H_];        // h double buffer (512 KB)

// ---------------- packed fp32x2 FMA (FFMA2 via PTX only) ----------------
__device__ __forceinline__ unsigned long long ffma2(
    unsigned long long a, unsigned long long b, unsigned long long c)
{
    unsigned long long d;
    asm("fma.rn.f32x2 %0, %1, %2, %3;" : "=l"(d) : "l"(a), "l"(b), "l"(c));
    return d;
}
__device__ __forceinline__ float2 unpack2(unsigned long long v) {
    float2 r;
    asm("mov.b64 {%0, %1}, %2;" : "=f"(r.x), "=f"(r.y) : "l"(v));
    return r;
}

// ---------------- init: zero h0 each launch (step 511 dirties buffer 0) ----------------
__global__ void init_h0_kernel() {
    int i = blockIdx.x * blockDim.x + threadIdx.x;
    if (i < B_ * H_) g_h[0][i] = 0.0f;
}

// ---------------- pre-GEMM (unchanged, proven): out[b][t][n] = x·Wi^T + bi + bh ----------
__global__ __launch_bounds__(256) void gemm_pre_kernel(
    const float* __restrict__ x, const float* __restrict__ Wi,
    const float* __restrict__ bi, const float* __restrict__ bh,
    float* __restrict__ out)
{
    __shared__ float As[16][68];
    __shared__ float Bs[16][68];

    const int tid = threadIdx.x;
    const int tx = tid & 15;
    const int ty = tid >> 4;
    const int mbase = blockIdx.y * 64;
    const int nbase = blockIdx.x * 64;

    const int lrow = tid >> 2;
    const int lkq  = (tid & 3) * 4;

    const int m_l = mbase + lrow;
    const float* arow = x + (size_t)(m_l & 63) * (T_ * I_) + (size_t)(m_l >> 6) * I_;
    const float* brow = Wi + (size_t)(nbase + lrow) * I_;

    float acc[4][4];
#pragma unroll
    for (int i = 0; i < 4; i++)
#pragma unroll
        for (int j = 0; j < 4; j++) acc[i][j] = 0.0f;

    for (int k0 = 0; k0 < I_; k0 += 16) {
        float4 a4 = *(const float4*)(arow + k0 + lkq);
        float4 b4 = *(const float4*)(brow + k0 + lkq);
        __syncthreads();
        As[lkq + 0][lrow] = a4.x; As[lkq + 1][lrow] = a4.y;
        As[lkq + 2][lrow] = a4.z; As[lkq + 3][lrow] = a4.w;
        Bs[lkq + 0][lrow] = b4.x; Bs[lkq + 1][lrow] = b4.y;
        Bs[lkq + 2][lrow] = b4.z; Bs[lkq + 3][lrow] = b4.w;
        __syncthreads();
#pragma unroll
        for (int kk = 0; kk < 16; kk++) {
            float a0 = As[kk][ty * 4 + 0], a1 = As[kk][ty * 4 + 1];
            float a2 = As[kk][ty * 4 + 2], a3 = As[kk][ty * 4 + 3];
            float b0 = Bs[kk][tx * 4 + 0], b1 = Bs[kk][tx * 4 + 1];
            float b2 = Bs[kk][tx * 4 + 2], b3 = Bs[kk][tx * 4 + 3];
            acc[0][0] += a0 * b0; acc[0][1] += a0 * b1; acc[0][2] += a0 * b2; acc[0][3] += a0 * b3;
            acc[1][0] += a1 * b0; acc[1][1] += a1 * b1; acc[1][2] += a1 * b2; acc[1][3] += a1 * b3;
            acc[2][0] += a2 * b0; acc[2][1] += a2 * b1; acc[2][2] += a2 * b2; acc[2][3] += a2 * b3;
            acc[3][0] += a3 * b0; acc[3][1] += a3 * b1; acc[3][2] += a3 * b2; acc[3][3] += a3 * b3;
        }
    }

    const int n0 = nbase + tx * 4;
    float bias0 = bi[n0 + 0] + bh[n0 + 0];
    float bias1 = bi[n0 + 1] + bh[n0 + 1];
    float bias2 = bi[n0 + 2] + bh[n0 + 2];
    float bias3 = bi[n0 + 3] + bh[n0 + 3];
#pragma unroll
    for (int i = 0; i < 4; i++) {
        int m = mbase + ty * 4 + i;
        int b = m & 63;
        int t = m >> 6;
        float4 o;
        o.x = acc[i][0] + bias0; o.y = acc[i][1] + bias1;
        o.z = acc[i][2] + bias2; o.w = acc[i][3] + bias3;
        *(float4*)(out + (size_t)b * (T_ * H_) + (size_t)t * H_ + n0) = o;
    }
}

// ---------------- per-step scan v2: smem-staged, k-split register-tiled ----------------
// grid 128 = 4 b-groups x 32 j-groups. Block tile: 16b x 32j x 1024k.
// Stage h slice (16x1024, 64KB) + Wh slice (32x1024, 128KB) into smem (bulk, coalesced).
// Compute: 8 warps = 8 k-segments (128k each); 32 lanes = tiles of 4b x 4j (strided:
// b in {bt,bt+4,bt+8,bt+12}, j in {jt,jt+8,jt+16,jt+24}) -> conflict-free LDS.
// k-packed FFMA2 accumulators; 8-way k reduction via smem; in-place pre+ReLU epilogue.
__global__ __launch_bounds__(SCAN_THREADS) void scan_step_kernel(
    const float* __restrict__ Wh,
    float* __restrict__ out,
    int t, int is_last)
{
    extern __shared__ float smem[];
    float* h_s = smem;                   // [16][HS_PITCH]
    float* w_s = smem + HS_FLOATS;       // [32][WS_PITCH]
    float* red = smem;                   // reduction area aliases h_s (after sync)

    const int tid = threadIdx.x;
    const int bg = blockIdx.x & 3;       // b-group (16 b each)
    const int jg = blockIdx.x >> 2;      // j-group (32 j each)

    // ---- stage h slice: 16 rows x 1024 floats ----
    {
        const float* hsrc = g_h[t & 1] + (size_t)(bg * BT_) * H_;
#pragma unroll
        for (int n = 0; n < 16; n++) {           // 4096 float4 / 256 thr
            int i = tid + n * SCAN_THREADS;
            int row = i >> 8, c4 = (i & 255) * 4;
            float4 v = *(const float4*)(hsrc + row * H_ + c4);
            *(float4*)(h_s + row * HS_PITCH + c4) = v;
        }
    }
    // ---- stage Wh slice: 32 rows x 1024 floats ----
    {
        const float* wsrc = Wh + (size_t)(jg * JT_) * H_;
#pragma unroll
        for (int n = 0; n < 32; n++) {           // 8192 float4 / 256 thr
            int i = tid + n * SCAN_THREADS;
            int row = i >> 8, c4 = (i & 255) * 4;
            float4 v = *(const float4*)(wsrc + row * H_ + c4);
            *(float4*)(w_s + row * WS_PITCH + c4) = v;
        }
    }
    __syncthreads();

    // ---- compute: thread = (kseg, bt, jt) ----
    const int lane = tid & 31;
    const int kseg = tid >> 5;           // 0..7, 128 k each
    const int bt = lane >> 3;            // 0..3
    const int jt = lane & 7;             // 0..7
    const int k0 = kseg * 128;

    const float* hp = h_s + k0;
    const float* wp = w_s + k0;

    unsigned long long acc[4][4];
#pragma unroll
    for (int i = 0; i < 4; i++)
#pragma unroll
        for (int m = 0; m < 4; m++) acc[i][m] = 0ull;

#pragma unroll 2
    for (int kk = 0; kk < 128; kk += 4) {
        ulonglong2 hq[4], wq[4];
#pragma unroll
        for (int i = 0; i < 4; i++)
            hq[i] = *(const ulonglong2*)(hp + (bt + 4 * i) * HS_PITCH + kk);
#pragma unroll
        for (int m = 0; m < 4; m++)
            wq[m] = *(const ulonglong2*)(wp + (jt + 8 * m) * WS_PITCH + kk);
#pragma unroll
        for (int i = 0; i < 4; i++)
#pragma unroll
            for (int m = 0; m < 4; m++) {
                acc[i][m] = ffma2(hq[i].x, wq[m].x, acc[i][m]);
                acc[i][m] = ffma2(hq[i].y, wq[m].y, acc[i][m]);
            }
    }

    // collapse packed lanes
    float sums[16];
#pragma unroll
    for (int i = 0; i < 4; i++)
#pragma unroll
        for (int m = 0; m < 4; m++) {
            float2 p = unpack2(acc[i][m]);
            sums[i * 4 + m] = p.x + p.y;
        }

    // ---- k-split reduction through smem (aliases h_s) ----
    __syncthreads();                      // everyone done reading h_s
#pragma unroll
    for (int o = 0; o < 16; o++)
        red[tid * 16 + o] = sums[o];      // red[(kseg*32+lane)*16 + o], 16 KB
    __syncthreads();

    // ---- epilogue: 2 outputs per thread ----
    float* hnext = g_h[(t + 1) & 1];
    float* hid = out + (size_t)B_ * T_ * H_;
#pragma unroll
    for (int r = 0; r < 2; r++) {
        int o = tid + r * SCAN_THREADS;   // 0..511
        int lane_o = o & 31;
        int idx = o >> 5;                 // 0..15 = i*4 + m
        float v = 0.0f;
#pragma unroll
        for (int s = 0; s < 8; s++)
            v += red[(s * 32 + lane_o) * 16 + idx];

        int bt_o = lane_o >> 3, jt_o = lane_o & 7;
        int ib = idx >> 2, im = idx & 3;
        int b = bg * BT_ + bt_o + 4 * ib;
        int j = jg * JT_ + jt_o + 8 * im;

        float* oel = out + (size_t)b * (T_ * H_) + (size_t)t * H_ + j;
        float val = fmaxf(v + *oel, 0.0f);
        *oel = val;
        hnext[b * H_ + j] = val;
        if (is_last) hid[b * H_ + j] = val;
    }
}

// ---------------- launch ----------------
extern "C" void kernel_launch(void* const* d_in, const int* in_sizes, int n_in,
                              void* d_out, int out_size)
{
    const float* x  = (const float*)d_in[0];
    const float* Wi = (const float*)d_in[1];
    const float* bi = (const float*)d_in[2];
    const float* Wh = (const float*)d_in[3];
    const float* bh = (const float*)d_in[4];
    float* out = (float*)d_out;

    // opt-in to >48KB dynamic smem for the scan kernel (idempotent, not a stream op)
    cudaFuncSetAttribute(scan_step_kernel,
                         cudaFuncAttributeMaxDynamicSharedMemorySize, SCAN_SMEM_BYTES);

    init_h0_kernel<<<64, 1024>>>();
    dim3 grid_gemm(H_ / 64, (T_ * B_) / 64);   // (16, 512)
    gemm_pre_kernel<<<grid_gemm, 256>>>(x, Wi, bi, bh, out);

    for (int t = 0; t < T_; t++) {
        scan_step_kernel<<<128, SCAN_THREADS, SCAN_SMEM_BYTES>>>(Wh, out, t, t == T_ - 1);
    }
}